// round 14
// baseline (speedup 1.0000x reference)
#include <cuda_runtime.h>
#include <cuda_fp16.h>
#include <cstdint>
#include <math.h>

// Problem dims
#define NB   32
#define NI   12
#define NVV  128
#define NHD  32
#define NTT  100
#define NHH  4096
#define NH3  12288
#define NR   3200
#define NBLK 128

// d_out region offsets (floats)
static const long OUT_STATES = 13107200L;
static const long OUT_HENC   = 26214400L;
static const long OUT_CLS    = 26345472L;

// ------------------------- scratch -----------------------------------------
__device__ float    gSupport[NVV * NVV];
__device__ __align__(256) __half gReprH[(long)NR * NHH];
__device__ __align__(256) __half gWih[(long)NH3 * NHH];
// W_hh block-tiled + SW128-swizzled (see init_whh_kernel)
__device__ __align__(256) __half gWhh[(long)NH3 * NHH];
__device__ __align__(256) float  gGx[(long)NR * NH3];
// h double-buffered, tiled [ktile 0..31][b 0..31][128] with SW128 swizzle:
// logical byte L = b*256 + (n&127)*2; physical P = L ^ (((L>>7)&7)<<4).
__device__ __align__(1024) __half gHh2[2][32 * NB * 128];
__device__ unsigned gBarCnt;
__device__ unsigned gBarPhase;

// ------------------------- asm helpers -------------------------------------
__device__ __forceinline__ uint64_t mk_evict_last_policy() {
    uint64_t pol;
    asm("createpolicy.fractional.L2::evict_last.b64 %0, 1.0;" : "=l"(pol));
    return pol;
}
__device__ __forceinline__ void cp_async16(void* smem, const void* gmem) {
    uint32_t s = (uint32_t)__cvta_generic_to_shared(smem);
    asm volatile("cp.async.cg.shared.global [%0], [%1], 16;\n" :: "r"(s), "l"(gmem));
}
__device__ __forceinline__ void cp_async16_el(void* smem, const void* gmem, uint64_t pol) {
    uint32_t s = (uint32_t)__cvta_generic_to_shared(smem);
    asm volatile("cp.async.cg.shared.global.L2::cache_hint [%0], [%1], 16, %2;\n"
                 :: "r"(s), "l"(gmem), "l"(pol));
}
__device__ __forceinline__ void cp_commit() {
    asm volatile("cp.async.commit_group;\n");
}
template <int N>
__device__ __forceinline__ void cp_wait() {
    asm volatile("cp.async.wait_group %0;\n" :: "n"(N));
}
__device__ __forceinline__ uint32_t smem_u32(const void* p) {
    return (uint32_t)__cvta_generic_to_shared(p);
}
__device__ __forceinline__ void ldsm_x4(uint32_t& r0, uint32_t& r1, uint32_t& r2,
                                        uint32_t& r3, uint32_t addr) {
    asm volatile("ldmatrix.sync.aligned.m8n8.x4.shared.b16 {%0,%1,%2,%3}, [%4];\n"
                 : "=r"(r0), "=r"(r1), "=r"(r2), "=r"(r3) : "r"(addr));
}
__device__ __forceinline__ void ldsm_x2(uint32_t& r0, uint32_t& r1, uint32_t addr) {
    asm volatile("ldmatrix.sync.aligned.m8n8.x2.shared.b16 {%0,%1}, [%2];\n"
                 : "=r"(r0), "=r"(r1) : "r"(addr));
}
__device__ __forceinline__ void mma_m16n8k16(float* d, const uint32_t* a,
                                             uint32_t b0, uint32_t b1) {
    asm volatile(
        "mma.sync.aligned.m16n8k16.row.col.f32.f16.f16.f32 "
        "{%0,%1,%2,%3}, {%4,%5,%6,%7}, {%8,%9}, {%0,%1,%2,%3};\n"
        : "+f"(d[0]), "+f"(d[1]), "+f"(d[2]), "+f"(d[3])
        : "r"(a[0]), "r"(a[1]), "r"(a[2]), "r"(a[3]), "r"(b0), "r"(b1));
}
__device__ __forceinline__ void mbar_init(uint32_t addr, uint32_t cnt) {
    asm volatile("mbarrier.init.shared.b64 [%0], %1;" :: "r"(addr), "r"(cnt) : "memory");
}
__device__ __forceinline__ void mbar_expect_tx(uint32_t addr, uint32_t bytes) {
    asm volatile("mbarrier.arrive.expect_tx.shared.b64 _, [%0], %1;"
                 :: "r"(addr), "r"(bytes) : "memory");
}
__device__ __forceinline__ void mbar_wait_parity(uint32_t addr, uint32_t parity) {
    uint32_t done;
    asm volatile(
        "{\n\t.reg .pred p;\n\t"
        "mbarrier.try_wait.parity.acquire.cta.shared::cta.b64 p, [%1], %2;\n\t"
        "selp.b32 %0, 1, 0, p;\n\t}"
        : "=r"(done) : "r"(addr), "r"(parity) : "memory");
    if (!done) {
        asm volatile(
            "{\n\t.reg .pred P1;\n\t"
            "WAIT_LOOP_%=:\n\t"
            "mbarrier.try_wait.parity.acquire.cta.shared::cta.b64 P1, [%0], %1, 0x989680;\n\t"
            "@P1 bra.uni WAIT_DONE_%=;\n\t"
            "bra.uni WAIT_LOOP_%=;\n\t"
            "WAIT_DONE_%=:\n\t}"
            :: "r"(addr), "r"(parity) : "memory");
    }
}
__device__ __forceinline__ void tma_bulk_1d(uint32_t smem_dst, const void* gsrc,
                                            uint32_t bytes, uint32_t mbar) {
    asm volatile(
        "cp.async.bulk.shared::cluster.global.mbarrier::complete_tx::bytes "
        "[%0], [%1], %2, [%3];"
        :: "r"(smem_dst), "l"(gsrc), "r"(bytes), "r"(mbar) : "memory");
}

// ------------------------- misc init: support + W_ih convert ----------------
__global__ void misc_init_kernel(const float4* __restrict__ wih4,
                                 const float* __restrict__ adj) {
    long gid = (long)blockIdx.x * blockDim.x + threadIdx.x;
    long stride = (long)gridDim.x * blockDim.x;

    if (blockIdx.x == 0 && threadIdx.x < NVV) {
        int w = threadIdx.x;
        float s = 0.f;
        for (int v = 0; v < NVV; v++) s += adj[w * NVV + v];
        float inv = 1.f / (s + 1e-6f);
        for (int v = 0; v < NVV; v++) gSupport[w * NVV + v] = adj[w * NVV + v] * inv;
    }

    long n4 = (long)NH3 * NHH / 4;
    __half2* wih_o = (__half2*)gWih;
    for (long i = gid; i < n4; i += stride) {
        float4 a = wih4[i];
        wih_o[2 * i]     = __floats2half2_rn(a.x, a.y);
        wih_o[2 * i + 1] = __floats2half2_rn(a.z, a.w);
    }
}

// ------------------------- W_hh tiler (coalesced) + h0 init ----------------
__global__ void __launch_bounds__(256) init_whh_kernel(const float* __restrict__ whh,
                                                       const float* __restrict__ h0) {
    __shared__ __half sh[32 * 128];   // 8KB tile (fp16)
    int tid = threadIdx.x;
    int bid = blockIdx.x;             // 12288 blocks

    // h0 init into tiled+swizzled layout (first 512 blocks)
    long gid = (long)bid * 256 + tid;
    if (gid < (long)NB * NHH) {
        int n = (int)(gid & (NHH - 1));
        int b = (int)(gid >> 12);
        int ktile = n >> 7, kl = n & 127;
        uint32_t L = (uint32_t)(b * 256 + kl * 2);
        uint32_t P = L ^ (((L >> 7) & 7) << 4);
        *(__half*)((char*)gHh2[0] + ktile * 8192 + P) = __float2half(h0[n]);
    }

    int gate = bid % 3;
    int kt   = (bid / 3) % 32;
    int j    = bid / 96;

    // coalesced load + convert: 8 threads per row, 16 floats each
    {
        int row = tid >> 3;
        int c0  = (tid & 7) * 16;
        const float4* src = (const float4*)(whh +
            ((long)gate * NHH + j * 32 + row) * (long)NHH + kt * 128 + c0);
        __half2* sp = (__half2*)(sh + row * 128 + c0);
        float4 v;
        v = src[0]; sp[0] = __floats2half2_rn(v.x, v.y); sp[1] = __floats2half2_rn(v.z, v.w);
        v = src[1]; sp[2] = __floats2half2_rn(v.x, v.y); sp[3] = __floats2half2_rn(v.z, v.w);
        v = src[2]; sp[4] = __floats2half2_rn(v.x, v.y); sp[5] = __floats2half2_rn(v.z, v.w);
        v = src[3]; sp[6] = __floats2half2_rn(v.x, v.y); sp[7] = __floats2half2_rn(v.z, v.w);
    }
    __syncthreads();

    // swizzled contiguous write: 512 x 16B stores, 2 per thread
#pragma unroll
    for (int w = 0; w < 2; w++) {
        int s = tid + w * 256;
        int khalf = s >> 8;
        int qoff  = (s & 255) * 16;
        int l = qoff ^ ((qoff >> 3) & 0x70);
        int r = l >> 7;
        int cl = (l & 127) >> 1;
        uint4 val = *(const uint4*)(sh + r * 128 + khalf * 64 + cl);
        *(uint4*)((char*)gWhh + (long)bid * 8192 + khalf * 4096 + qoff) = val;
    }
}

// ------------------------- repr --------------------------------------------
__global__ void repr_kernel(const float* __restrict__ x,
                            const float* __restrict__ conv_w,
                            const float* __restrict__ conv_b,
                            float* __restrict__ d_out) {
    extern __shared__ float sm[];
    float* supT = sm;
    float* bufA = supT + 128 * 129;
    float* bufB = bufA + 32 * 132;
    float* xs   = bufB + 32 * 132;

    int r = blockIdx.x;
    int t = r >> 5;
    int b = r & 31;
    int tid = threadIdx.x;

    for (int idx = tid; idx < NI * NVV; idx += 256) {
        int i = idx >> 7, v = idx & 127;
        xs[idx] = x[(((long)b * NI + i) * NVV + v) * NTT + t];
    }
    for (int idx = tid; idx < NVV * NVV; idx += 256) {
        int w = idx >> 7, v = idx & 127;
        supT[v * 129 + w] = gSupport[idx];
    }
    __syncthreads();

    for (int idx = tid; idx < NHD * NVV; idx += 256) {
        int h = idx >> 7, v = idx & 127;
        float a = conv_b[h];
#pragma unroll
        for (int i = 0; i < NI; i++) a += conv_w[h * NI + i] * xs[i * NVV + v];
        bufA[h * 132 + v] = a;
    }
    __syncthreads();

    int w0 = tid & 31;
    int h0 = tid >> 5;

    float acc1[4][4];
#pragma unroll
    for (int i = 0; i < 4; i++)
#pragma unroll
        for (int j = 0; j < 4; j++) acc1[i][j] = 0.f;
    for (int v = 0; v < NVV; v++) {
        float a[4], s[4];
#pragma unroll
        for (int i = 0; i < 4; i++) a[i] = bufA[(h0 + 8 * i) * 132 + v];
#pragma unroll
        for (int j = 0; j < 4; j++) s[j] = supT[v * 129 + w0 + 32 * j];
#pragma unroll
        for (int i = 0; i < 4; i++)
#pragma unroll
            for (int j = 0; j < 4; j++) acc1[i][j] += a[i] * s[j];
    }
    __syncthreads();
#pragma unroll
    for (int i = 0; i < 4; i++)
#pragma unroll
        for (int j = 0; j < 4; j++) bufB[(h0 + 8 * i) * 132 + w0 + 32 * j] = acc1[i][j];
    __syncthreads();

    float acc2[4][4];
#pragma unroll
    for (int i = 0; i < 4; i++)
#pragma unroll
        for (int j = 0; j < 4; j++) acc2[i][j] = 0.f;
    for (int v = 0; v < NVV; v++) {
        float a[4], s[4];
#pragma unroll
        for (int i = 0; i < 4; i++) a[i] = bufB[(h0 + 8 * i) * 132 + v];
#pragma unroll
        for (int j = 0; j < 4; j++) s[j] = supT[v * 129 + w0 + 32 * j];
#pragma unroll
        for (int i = 0; i < 4; i++)
#pragma unroll
            for (int j = 0; j < 4; j++) acc2[i][j] += a[i] * s[j];
    }

#pragma unroll
    for (int i = 0; i < 4; i++) {
#pragma unroll
        for (int j = 0; j < 4; j++) {
            int h = h0 + 8 * i, w = w0 + 32 * j;
            int n = h * NVV + w;
            float val = acc2[i][j];
            d_out[(long)b * (NHH * NTT) + (long)n * NTT + t] = val;
            gReprH[(long)r * NHH + n] = __float2half(val);
        }
    }
}

// ------------------------- pipelined gx GEMM (ST=3, 2 CTA/SM) --------------
__global__ void __launch_bounds__(256, 2) gemm_gx_kernel(const float* __restrict__ bias) {
    constexpr int BM = 128, BN = 128, BK = 64, ST = 3, LD = 72;
    extern __shared__ __half smh[];
    __half* As = smh;
    __half* Ws = smh + ST * BM * LD;

    int tid = threadIdx.x;
    int warp = tid >> 5, lane = tid & 31;
    int g = lane >> 2, ti = lane & 3;
    int wm = warp & 1, wn = warp >> 1;

    long rowA0 = (long)blockIdx.x * BM;
    long rowW0 = (long)blockIdx.y * BN;

    const __half* A = gReprH;
    const __half* W = gWih;

    int ldrow = tid >> 3, ldseg = tid & 7;
    uint64_t pol = mk_evict_last_policy();

    uint32_t aoff[4];
#pragma unroll
    for (int mt = 0; mt < 4; mt++)
        aoff[mt] = (wm * 64 + mt * 16 + (lane & 15)) * LD + (lane >> 4) * 8;
    uint32_t woff[2];
#pragma unroll
    for (int pr = 0; pr < 2; pr++)
        woff[pr] = (wn * 32 + pr * 16 + ((lane >> 4) & 1) * 8 + (lane & 7)) * LD
                   + ((lane >> 3) & 1) * 8;

    uint32_t As_base = smem_u32(As);
    uint32_t Ws_base = smem_u32(Ws);

#pragma unroll
    for (int s = 0; s < ST - 1; s++) {
        int k0 = s * BK;
#pragma unroll
        for (int i = 0; i < 4; i++) {
            int row = ldrow + i * 32;
            cp_async16_el(As + (s * BM + row) * LD + ldseg * 8,
                          A + (rowA0 + row) * (long)NHH + k0 + ldseg * 8, pol);
        }
#pragma unroll
        for (int i = 0; i < 4; i++) {
            int row = ldrow + i * 32;
            cp_async16(Ws + (s * BN + row) * LD + ldseg * 8,
                       W + (rowW0 + row) * (long)NHH + k0 + ldseg * 8);
        }
        cp_commit();
    }

    float acc[4][4][4];
#pragma unroll
    for (int mt = 0; mt < 4; mt++)
#pragma unroll
        for (int nt = 0; nt < 4; nt++)
#pragma unroll
            for (int q = 0; q < 4; q++) acc[mt][nt][q] = 0.f;

    const int KT = NHH / BK;
    for (int kt = 0; kt < KT; kt++) {
        cp_wait<ST - 2>();
        __syncthreads();
        if (kt + ST - 1 < KT) {
            int s = (kt + ST - 1) % ST;
            int k0 = (kt + ST - 1) * BK;
#pragma unroll
            for (int i = 0; i < 4; i++) {
                int row = ldrow + i * 32;
                cp_async16_el(As + (s * BM + row) * LD + ldseg * 8,
                              A + (rowA0 + row) * (long)NHH + k0 + ldseg * 8, pol);
            }
#pragma unroll
            for (int i = 0; i < 4; i++) {
                int row = ldrow + i * 32;
                cp_async16(Ws + (s * BN + row) * LD + ldseg * 8,
                           W + (rowW0 + row) * (long)NHH + k0 + ldseg * 8);
            }
        }
        cp_commit();  // every iter (tail alignment)

        uint32_t Ab = As_base + (uint32_t)((kt % ST) * BM * LD) * 2;
        uint32_t Wb = Ws_base + (uint32_t)((kt % ST) * BN * LD) * 2;

#pragma unroll
        for (int kk = 0; kk < BK; kk += 16) {
            uint32_t af[4][4];
#pragma unroll
            for (int mt = 0; mt < 4; mt++)
                ldsm_x4(af[mt][0], af[mt][1], af[mt][2], af[mt][3],
                        Ab + (aoff[mt] + kk) * 2);
            uint32_t bf[4][2];
#pragma unroll
            for (int pr = 0; pr < 2; pr++)
                ldsm_x4(bf[2 * pr][0], bf[2 * pr][1], bf[2 * pr + 1][0], bf[2 * pr + 1][1],
                        Wb + (woff[pr] + kk) * 2);
#pragma unroll
            for (int nt = 0; nt < 4; nt++)
#pragma unroll
                for (int mt = 0; mt < 4; mt++)
                    mma_m16n8k16(acc[mt][nt], af[mt], bf[nt][0], bf[nt][1]);
        }
    }

    float* C = gGx;
#pragma unroll
    for (int mt = 0; mt < 4; mt++) {
        long row = rowA0 + wm * 64 + mt * 16 + g;
#pragma unroll
        for (int nt = 0; nt < 4; nt++) {
            long col = rowW0 + wn * 32 + nt * 8 + 2 * ti;
            float bv0 = bias[col], bv1 = bias[col + 1];
            __stcs(&C[row * NH3 + col],           acc[mt][nt][0] + bv0);
            __stcs(&C[row * NH3 + col + 1],       acc[mt][nt][1] + bv1);
            __stcs(&C[(row + 8) * NH3 + col],     acc[mt][nt][2] + bv0);
            __stcs(&C[(row + 8) * NH3 + col + 1], acc[mt][nt][3] + bv1);
        }
    }
}

// ------------------------- persistent GRU: all-TMA, BK=256 ------------------
// 16 iterations/step. W: 3-stage ring of 48KB (two contiguous pre-swizzled
// tiles -> ONE bulk). A(h): 3-stage ring of 16KB (tiled+swizzled h layout,
// one bulk). One shared consumer cursor; producers (tid0) track seq%3.
// W issues cross the step barrier (same data every step); next-step A pairs
// 0,1 issue post-barrier.
__global__ void __launch_bounds__(256) gru_persistent_kernel(
    const float* __restrict__ h0,
    const float* __restrict__ b_hh,
    float* __restrict__ d_out) {
    constexpr int NIT = 16;                 // iterations per step (BK=256)
    constexpr int WST = 49152, AST = 16384; // stage sizes (bytes)
    extern __shared__ __align__(1024) char smraw[];
    __half* Ws   = (__half*)smraw;                        // 3*49152 = 147456
    char*   Asb  = smraw + 147456;                        // 3*16384 = 49152
    float*  gh_s = (float*)(smraw + 196608);              // 12800
    uint32_t bars = smem_u32(smraw + 209408);             // fullW[3]@0, fullA[3]@24
    float*  sbuf = (float*)(smraw + 209472);              // 16384

    int tid = threadIdx.x;
    int warp = tid >> 5, lane = tid & 31;
    int g = lane >> 2, ti = lane & 3;
    int wm = warp & 1, wn = warp >> 1;
    int n0 = blockIdx.x * 32;

    // W ldmatrix lane constants (within one 24KB tile)
    int row4 = wn * 24 + ((lane >> 4) & 1) * 8 + (lane & 7);
    uint32_t wbase4 = (uint32_t)((row4 >> 5) * 8192 + (row4 & 31) * 128);
    uint32_t swz4   = (uint32_t)(((row4 & 31) & 7) << 4);
    uint32_t cb4    = ((lane >> 3) & 1) * 16;
    int row2 = wn * 24 + 16 + (lane & 7);
    uint32_t wbase2 = (uint32_t)((row2 >> 5) * 8192 + (row2 & 31) * 128);
    uint32_t swz2   = (uint32_t)(((row2 & 31) & 7) << 4);
    uint32_t cb2    = ((lane >> 3) & 1) * 16;

    // A ldmatrix lane base (bytes within one 8KB tile, pre-swizzle)
    uint32_t abase = (uint32_t)((wm * 16 + (lane & 15)) * 256 + (lane >> 4) * 16);

    uint32_t Ws_base = smem_u32(Ws);
    uint32_t As_base = smem_u32(Asb);

    int pb[4], pn[4];
    float hreg[4], bhr[4], bhz[4], bhn[4];
#pragma unroll
    for (int i = 0; i < 4; i++) {
        int idx = tid + i * 256;
        pb[i] = idx >> 5;
        pn[i] = n0 + (idx & 31);
        hreg[i] = h0[pn[i]];
        bhr[i] = b_hh[pn[i]];
        bhz[i] = b_hh[NHH + pn[i]];
        bhn[i] = b_hh[2 * NHH + pn[i]];
    }

    unsigned barBase = *(volatile unsigned*)&gBarPhase;
    const char* wsrc = (const char*)(gWhh + (long)blockIdx.x * 32 * 12288);

    if (tid == 0) {
        for (int s = 0; s < 3; s++) { mbar_init(bars + 8 * s, 1);        // fullW
                                      mbar_init(bars + 24 + 8 * s, 1); } // fullA
    }
    __syncthreads();
    asm volatile("fence.proxy.async.shared::cta;" ::: "memory");

    // producer slot cursors (tid0 only)
    int wslot = 0, aslot = 0;
    // consumer cursor + parity (all threads; W and A share it)
    int cs = 0, ph = 0;

    // prologue: W pairs 0,1 and A pairs 0,1 into slots 0,1
    if (tid == 0) {
#pragma unroll
        for (int p = 0; p < 2; p++) {
            mbar_expect_tx(bars + 8 * wslot, WST);
            tma_bulk_1d(Ws_base + wslot * WST, wsrc + (long)p * WST, WST,
                        bars + 8 * wslot);
            wslot++;
            mbar_expect_tx(bars + 24 + 8 * aslot, AST);
            tma_bulk_1d(As_base + aslot * AST, (const char*)gHh2[0] + p * AST, AST,
                        bars + 24 + 8 * aslot);
            aslot++;
        }
    }

    for (int t = 0; t < NTT; t++) {
        const char* Ainb = (const char*)gHh2[t & 1];

        float pxr[4], pxz[4], pxn[4];
#pragma unroll
        for (int i = 0; i < 4; i++) {
            long gxr = ((long)(t * NB + pb[i])) * NH3 + pn[i];
            pxr[i] = __ldcs(&gGx[gxr]);
            pxz[i] = __ldcs(&gGx[gxr + NHH]);
            pxn[i] = __ldcs(&gGx[gxr + 2 * NHH]);
        }

        float acc[3][4];
#pragma unroll
        for (int nt = 0; nt < 3; nt++)
#pragma unroll
            for (int q = 0; q < 4; q++) acc[nt][q] = 0.f;

        for (int it = 0; it < NIT; it++) {
            mbar_wait_parity(bars + 8 * cs, (uint32_t)ph);        // W ready
            mbar_wait_parity(bars + 24 + 8 * cs, (uint32_t)ph);   // A ready
            __syncthreads();  // all warps past previous iteration's slot

            if (tid == 0) {
                // W issue (crosses step barrier; data identical each step)
                if (t < NTT - 1 || it < NIT - 2) {
                    int pw = (it + 2) & (NIT - 1);
                    mbar_expect_tx(bars + 8 * wslot, WST);
                    tma_bulk_1d(Ws_base + wslot * WST, wsrc + (long)pw * WST,
                                WST, bars + 8 * wslot);
                    wslot++; if (wslot == 3) wslot = 0;
                }
                // A issue (current step only)
                if (it < NIT - 2) {
                    mbar_expect_tx(bars + 24 + 8 * aslot, AST);
                    tma_bulk_1d(As_base + aslot * AST, Ainb + (it + 2) * AST,
                                AST, bars + 24 + 8 * aslot);
                    aslot++; if (aslot == 3) aslot = 0;
                }
            }

            uint32_t Wb = Ws_base + (uint32_t)(cs * WST);
            uint32_t Ab = As_base + (uint32_t)(cs * AST);

#pragma unroll
            for (int kk = 0; kk < 256; kk += 16) {
                uint32_t half_off = (uint32_t)(kk >> 7);
                uint32_t kkl = (uint32_t)(kk & 127);

                uint32_t aL = abase + kkl * 2;
                uint32_t aP = aL ^ (((aL >> 7) & 7) << 4);
                uint32_t af[4];
                ldsm_x4(af[0], af[1], af[2], af[3], Ab + half_off * 8192 + aP);

                uint32_t wtile = half_off * 24576;
                uint32_t khb = (uint32_t)((kkl >> 6) * 4096);
                uint32_t klb = (uint32_t)((kkl & 63) * 2);
                uint32_t b00, b01, b10, b11, b20, b21;
                ldsm_x4(b00, b01, b10, b11,
                        Wb + wtile + wbase4 + khb + ((cb4 + klb) ^ swz4));
                ldsm_x2(b20, b21,
                        Wb + wtile + wbase2 + khb + ((cb2 + klb) ^ swz2));
                mma_m16n8k16(acc[0], af, b00, b01);
                mma_m16n8k16(acc[1], af, b10, b11);
                mma_m16n8k16(acc[2], af, b20, b21);
            }
            cs++; if (cs == 3) { cs = 0; ph ^= 1; }
        }

        // gh -> smem
#pragma unroll
        for (int nt = 0; nt < 3; nt++) {
            int c = (wn * 3 + nt) * 8 + 2 * ti;
            int m = wm * 16 + g;
            gh_s[m * 100 + c]           = acc[nt][0];
            gh_s[m * 100 + c + 1]       = acc[nt][1];
            gh_s[(m + 8) * 100 + c]     = acc[nt][2];
            gh_s[(m + 8) * 100 + c + 1] = acc[nt][3];
        }
        __syncthreads();

        __half* Aout = gHh2[(t + 1) & 1];
        int tph = t & 3;
#pragma unroll
        for (int i = 0; i < 4; i++) {
            int idx = tid + i * 256;
            int b = pb[i], nl = pn[i] - n0, n = pn[i];

            float hr = gh_s[b * 100 + nl]      + bhr[i];
            float hz = gh_s[b * 100 + 32 + nl] + bhz[i];
            float hn = gh_s[b * 100 + 64 + nl] + bhn[i];

            float r = 1.f / (1.f + expf(-(pxr[i] + hr)));
            float z = 1.f / (1.f + expf(-(pxz[i] + hz)));
            float nn = tanhf(pxn[i] + r * hn);
            float hnew = (1.f - z) * nn + z * hreg[i];
            hreg[i] = hnew;

            // h -> tiled+swizzled layout
            int ktile = n >> 7, kl = n & 127;
            uint32_t L = (uint32_t)(b * 256 + kl * 2);
            uint32_t P = L ^ (((L >> 7) & 7) << 4);
            *(__half*)((char*)Aout + ktile * 8192 + P) = __float2half(hnew);

            sbuf[tph * 1024 + idx] = hnew;
            if (t == NTT - 1) d_out[OUT_HENC + b * NHH + n] = hnew;
        }

        // batched states flush every 4 steps
        if (tph == 3) {
#pragma unroll
            for (int i = 0; i < 4; i++) {
                int idx = tid + i * 256;
                int b = pb[i], n = pn[i];
                float4 v = make_float4(sbuf[idx], sbuf[1024 + idx],
                                       sbuf[2048 + idx], sbuf[3072 + idx]);
                __stcs((float4*)&d_out[OUT_STATES + (long)b * (NHH * NTT)
                                       + (long)n * NTT + (t - 3)], v);
            }
        }

        if (t < NTT - 1) {
            __threadfence();
            __syncthreads();
            if (tid == 0) {
                unsigned arrived = atomicAdd(&gBarCnt, 1u);
                unsigned target = barBase + (unsigned)(t + 1);
                if (arrived == NBLK - 1) {
                    gBarCnt = 0;
                    __threadfence();
                    atomicExch(&gBarPhase, target);
                } else {
                    while ((int)(atomicAdd(&gBarPhase, 0u) - target) < 0) {
                        __nanosleep(32);
                    }
                }
            }
            __syncthreads();

            // A prologue for next step (h now globally ready): pairs 0,1
            if (tid == 0) {
                const char* a2 = (const char*)gHh2[(t + 1) & 1];
#pragma unroll
                for (int p = 0; p < 2; p++) {
                    mbar_expect_tx(bars + 24 + 8 * aslot, AST);
                    tma_bulk_1d(As_base + aslot * AST, a2 + p * AST, AST,
                                bars + 24 + 8 * aslot);
                    aslot++; if (aslot == 3) aslot = 0;
                }
            }
        }
    }
}

// ------------------------- classifier ---------------------------------------
__global__ void classifier_kernel(const float* __restrict__ w1, const float* __restrict__ b1,
                                  const float* __restrict__ w2, const float* __restrict__ b2,
                                  float* __restrict__ d_out) {
    __shared__ float hid[300];
    int b = blockIdx.x;
    int tid = threadIdx.x, warp = tid >> 5, lane = tid & 31;
    const float* hb = d_out + OUT_HENC + (long)b * NHH;

    for (int j = warp; j < 300; j += 8) {
        float s = 0.f;
        for (int k = lane; k < NHH; k += 32) s += hb[k] * w1[(long)j * NHH + k];
#pragma unroll
        for (int off = 16; off; off >>= 1) s += __shfl_xor_sync(0xffffffffu, s, off);
        if (lane == 0) hid[j] = fmaxf(s + b1[j], 0.f);
    }
    __syncthreads();
    if (warp < 2) {
        float s = 0.f;
        for (int j = lane; j < 300; j += 32) s += hid[j] * w2[warp * 300 + j];
#pragma unroll
        for (int off = 16; off; off >>= 1) s += __shfl_xor_sync(0xffffffffu, s, off);
        if (lane == 0) d_out[OUT_CLS + b * 2 + warp] = s + b2[warp];
    }
}

// ------------------------- launch --------------------------------------------
extern "C" void kernel_launch(void* const* d_in, const int* in_sizes, int n_in,
                              void* d_out, int out_size) {
    const float* x      = (const float*)d_in[0];
    const float* adj    = (const float*)d_in[1];
    const float* h0     = (const float*)d_in[3];
    const float* conv_w = (const float*)d_in[4];
    const float* conv_b = (const float*)d_in[5];
    const float* w_ih   = (const float*)d_in[6];
    const float* w_hh   = (const float*)d_in[7];
    const float* b_ih   = (const float*)d_in[8];
    const float* b_hh   = (const float*)d_in[9];
    const float* cls_w1 = (const float*)d_in[10];
    const float* cls_b1 = (const float*)d_in[11];
    const float* cls_w2 = (const float*)d_in[12];
    const float* cls_b2 = (const float*)d_in[13];
    float* out = (float*)d_out;

    const int REPR_SMEM = (128 * 129 + 32 * 132 + 32 * 132 + 12 * 128) * 4;  // 105984
    const int GX_SMEM   = 3 * (128 + 128) * 72 * 2;                          // 110592
    const int PS_SMEM   = 209472 + 16384;                                    // 225856
    cudaFuncSetAttribute(repr_kernel, cudaFuncAttributeMaxDynamicSharedMemorySize, REPR_SMEM);
    cudaFuncSetAttribute(gemm_gx_kernel, cudaFuncAttributeMaxDynamicSharedMemorySize, GX_SMEM);
    cudaFuncSetAttribute(gru_persistent_kernel, cudaFuncAttributeMaxDynamicSharedMemorySize, PS_SMEM);

    // Launch order: gemm_gx at index 3 (the ncu capture slot).
    misc_init_kernel<<<2048, 256>>>((const float4*)w_ih, adj);
    init_whh_kernel<<<12288, 256>>>(w_hh, h0);
    repr_kernel<<<NR, 256, REPR_SMEM>>>(x, conv_w, conv_b, out);
    gemm_gx_kernel<<<dim3(25, 96), 256, GX_SMEM>>>(b_ih);
    gru_persistent_kernel<<<NBLK, 256, PS_SMEM>>>(h0, b_hh, out);
    classifier_kernel<<<NB, 256>>>(cls_w1, cls_b1, cls_w2, cls_b2, out);
}

// round 16
// speedup vs baseline: 1.0112x; 1.0112x over previous
#include <cuda_runtime.h>
#include <cuda_fp16.h>
#include <cstdint>
#include <math.h>

// Problem dims
#define NB   32
#define NI   12
#define NVV  128
#define NHD  32
#define NTT  100
#define NHH  4096
#define NH3  12288
#define NR   3200
#define NBLK 128

// d_out region offsets (floats)
static const long OUT_STATES = 13107200L;
static const long OUT_HENC   = 26214400L;
static const long OUT_CLS    = 26345472L;

// ------------------------- scratch -----------------------------------------
__device__ float    gSupport[NVV * NVV];
__device__ __align__(256) __half gReprH[(long)NR * NHH];
__device__ __align__(256) __half gWih[(long)NH3 * NHH];
// W_hh block-tiled + SW128-swizzled (see init_whh_kernel)
__device__ __align__(256) __half gWhh[(long)NH3 * NHH];
__device__ __align__(256) float  gGx[(long)NR * NH3];
__device__ __align__(256) __half gHh[2][NB * NHH];
__device__ unsigned gBarCnt;
__device__ unsigned gBarPhase;

// ------------------------- asm helpers -------------------------------------
__device__ __forceinline__ uint64_t mk_evict_last_policy() {
    uint64_t pol;
    asm("createpolicy.fractional.L2::evict_last.b64 %0, 1.0;" : "=l"(pol));
    return pol;
}
__device__ __forceinline__ void cp_async16(void* smem, const void* gmem) {
    uint32_t s = (uint32_t)__cvta_generic_to_shared(smem);
    asm volatile("cp.async.cg.shared.global [%0], [%1], 16;\n" :: "r"(s), "l"(gmem));
}
__device__ __forceinline__ void cp_async16_el(void* smem, const void* gmem, uint64_t pol) {
    uint32_t s = (uint32_t)__cvta_generic_to_shared(smem);
    asm volatile("cp.async.cg.shared.global.L2::cache_hint [%0], [%1], 16, %2;\n"
                 :: "r"(s), "l"(gmem), "l"(pol));
}
__device__ __forceinline__ void cp_commit() {
    asm volatile("cp.async.commit_group;\n");
}
template <int N>
__device__ __forceinline__ void cp_wait() {
    asm volatile("cp.async.wait_group %0;\n" :: "n"(N));
}
__device__ __forceinline__ uint32_t smem_u32(const void* p) {
    return (uint32_t)__cvta_generic_to_shared(p);
}
__device__ __forceinline__ void ldsm_x4(uint32_t& r0, uint32_t& r1, uint32_t& r2,
                                        uint32_t& r3, uint32_t addr) {
    asm volatile("ldmatrix.sync.aligned.m8n8.x4.shared.b16 {%0,%1,%2,%3}, [%4];\n"
                 : "=r"(r0), "=r"(r1), "=r"(r2), "=r"(r3) : "r"(addr));
}
__device__ __forceinline__ void ldsm_x2(uint32_t& r0, uint32_t& r1, uint32_t addr) {
    asm volatile("ldmatrix.sync.aligned.m8n8.x2.shared.b16 {%0,%1}, [%2];\n"
                 : "=r"(r0), "=r"(r1) : "r"(addr));
}
__device__ __forceinline__ void mma_m16n8k16(float* d, const uint32_t* a,
                                             uint32_t b0, uint32_t b1) {
    asm volatile(
        "mma.sync.aligned.m16n8k16.row.col.f32.f16.f16.f32 "
        "{%0,%1,%2,%3}, {%4,%5,%6,%7}, {%8,%9}, {%0,%1,%2,%3};\n"
        : "+f"(d[0]), "+f"(d[1]), "+f"(d[2]), "+f"(d[3])
        : "r"(a[0]), "r"(a[1]), "r"(a[2]), "r"(a[3]), "r"(b0), "r"(b1));
}
__device__ __forceinline__ void mbar_init(uint32_t addr, uint32_t cnt) {
    asm volatile("mbarrier.init.shared.b64 [%0], %1;" :: "r"(addr), "r"(cnt) : "memory");
}
__device__ __forceinline__ void mbar_expect_tx(uint32_t addr, uint32_t bytes) {
    asm volatile("mbarrier.arrive.expect_tx.shared.b64 _, [%0], %1;"
                 :: "r"(addr), "r"(bytes) : "memory");
}
__device__ __forceinline__ void mbar_wait_parity(uint32_t addr, uint32_t parity) {
    uint32_t done;
    asm volatile(
        "{\n\t.reg .pred p;\n\t"
        "mbarrier.try_wait.parity.acquire.cta.shared::cta.b64 p, [%1], %2;\n\t"
        "selp.b32 %0, 1, 0, p;\n\t}"
        : "=r"(done) : "r"(addr), "r"(parity) : "memory");
    if (!done) {
        asm volatile(
            "{\n\t.reg .pred P1;\n\t"
            "WAIT_LOOP_%=:\n\t"
            "mbarrier.try_wait.parity.acquire.cta.shared::cta.b64 P1, [%0], %1, 0x989680;\n\t"
            "@P1 bra.uni WAIT_DONE_%=;\n\t"
            "bra.uni WAIT_LOOP_%=;\n\t"
            "WAIT_DONE_%=:\n\t}"
            :: "r"(addr), "r"(parity) : "memory");
    }
}
__device__ __forceinline__ void tma_bulk_1d(uint32_t smem_dst, const void* gsrc,
                                            uint32_t bytes, uint32_t mbar) {
    asm volatile(
        "cp.async.bulk.shared::cluster.global.mbarrier::complete_tx::bytes "
        "[%0], [%1], %2, [%3];"
        :: "r"(smem_dst), "l"(gsrc), "r"(bytes), "r"(mbar) : "memory");
}

// ------------------------- support -------------------------------------------
__global__ void support_kernel(const float* __restrict__ adj) {
    int w = threadIdx.x;  // 128 threads
    float s = 0.f;
    for (int v = 0; v < NVV; v++) s += adj[w * NVV + v];
    float inv = 1.f / (s + 1e-6f);
    for (int v = 0; v < NVV; v++) gSupport[w * NVV + v] = adj[w * NVV + v] * inv;
}

// ------------------------- W_ih convert --------------------------------------
__global__ void wih_convert_kernel(const float4* __restrict__ wih4) {
    long gid = (long)blockIdx.x * blockDim.x + threadIdx.x;
    long stride = (long)gridDim.x * blockDim.x;
    long n4 = (long)NH3 * NHH / 4;
    __half2* wih_o = (__half2*)gWih;
    for (long i = gid; i < n4; i += stride) {
        float4 a = wih4[i];
        wih_o[2 * i]     = __floats2half2_rn(a.x, a.y);
        wih_o[2 * i + 1] = __floats2half2_rn(a.z, a.w);
    }
}

// ------------------------- W_hh tiler (coalesced) + h0 init ----------------
// Block bid = j*96 + kt*3 + gate handles one 32x128 fp32 tile of W_hh:
// rows gate*4096 + j*32 + [0,32), cols kt*128 + [0,128).
// Emits 2 pre-swizzled contiguous 4KB chunks at gWhh + bid*8192 (+khalf*4096).
__global__ void __launch_bounds__(256) init_whh_kernel(const float* __restrict__ whh,
                                                       const float* __restrict__ h0) {
    __shared__ __half sh[32 * 128];   // 8KB tile (fp16)
    int tid = threadIdx.x;
    int bid = blockIdx.x;             // 12288 blocks

    // h0 init (first 512 blocks)
    long gid = (long)bid * 256 + tid;
    if (gid < (long)NB * NHH) gHh[0][gid] = __float2half(h0[gid & (NHH - 1)]);

    int gate = bid % 3;
    int kt   = (bid / 3) % 32;
    int j    = bid / 96;

    // coalesced load + convert: 8 threads per row, 16 floats each
    {
        int row = tid >> 3;
        int c0  = (tid & 7) * 16;
        const float4* src = (const float4*)(whh +
            ((long)gate * NHH + j * 32 + row) * (long)NHH + kt * 128 + c0);
        __half2* sp = (__half2*)(sh + row * 128 + c0);
        float4 v;
        v = src[0]; sp[0] = __floats2half2_rn(v.x, v.y); sp[1] = __floats2half2_rn(v.z, v.w);
        v = src[1]; sp[2] = __floats2half2_rn(v.x, v.y); sp[3] = __floats2half2_rn(v.z, v.w);
        v = src[2]; sp[4] = __floats2half2_rn(v.x, v.y); sp[5] = __floats2half2_rn(v.z, v.w);
        v = src[3]; sp[6] = __floats2half2_rn(v.x, v.y); sp[7] = __floats2half2_rn(v.z, v.w);
    }
    __syncthreads();

    // swizzled contiguous write: 512 x 16B stores, 2 per thread
#pragma unroll
    for (int w = 0; w < 2; w++) {
        int s = tid + w * 256;
        int khalf = s >> 8;
        int qoff  = (s & 255) * 16;
        int l = qoff ^ ((qoff >> 3) & 0x70);
        int r = l >> 7;
        int cl = (l & 127) >> 1;
        uint4 val = *(const uint4*)(sh + r * 128 + khalf * 64 + cl);
        *(uint4*)((char*)gWhh + (long)bid * 8192 + khalf * 4096 + qoff) = val;
    }
}

// ------------------------- repr (ncu capture slot this round) ----------------
__global__ void repr_kernel(const float* __restrict__ x,
                            const float* __restrict__ conv_w,
                            const float* __restrict__ conv_b,
                            float* __restrict__ d_out) {
    extern __shared__ float sm[];
    float* supT = sm;
    float* bufA = supT + 128 * 129;
    float* bufB = bufA + 32 * 132;
    float* xs   = bufB + 32 * 132;

    int r = blockIdx.x;
    int t = r >> 5;
    int b = r & 31;
    int tid = threadIdx.x;

    for (int idx = tid; idx < NI * NVV; idx += 256) {
        int i = idx >> 7, v = idx & 127;
        xs[idx] = x[(((long)b * NI + i) * NVV + v) * NTT + t];
    }
    for (int idx = tid; idx < NVV * NVV; idx += 256) {
        int w = idx >> 7, v = idx & 127;
        supT[v * 129 + w] = gSupport[idx];
    }
    __syncthreads();

    for (int idx = tid; idx < NHD * NVV; idx += 256) {
        int h = idx >> 7, v = idx & 127;
        float a = conv_b[h];
#pragma unroll
        for (int i = 0; i < NI; i++) a += conv_w[h * NI + i] * xs[i * NVV + v];
        bufA[h * 132 + v] = a;
    }
    __syncthreads();

    int w0 = tid & 31;
    int h0 = tid >> 5;

    float acc1[4][4];
#pragma unroll
    for (int i = 0; i < 4; i++)
#pragma unroll
        for (int j = 0; j < 4; j++) acc1[i][j] = 0.f;
    for (int v = 0; v < NVV; v++) {
        float a[4], s[4];
#pragma unroll
        for (int i = 0; i < 4; i++) a[i] = bufA[(h0 + 8 * i) * 132 + v];
#pragma unroll
        for (int j = 0; j < 4; j++) s[j] = supT[v * 129 + w0 + 32 * j];
#pragma unroll
        for (int i = 0; i < 4; i++)
#pragma unroll
            for (int j = 0; j < 4; j++) acc1[i][j] += a[i] * s[j];
    }
    __syncthreads();
#pragma unroll
    for (int i = 0; i < 4; i++)
#pragma unroll
        for (int j = 0; j < 4; j++) bufB[(h0 + 8 * i) * 132 + w0 + 32 * j] = acc1[i][j];
    __syncthreads();

    float acc2[4][4];
#pragma unroll
    for (int i = 0; i < 4; i++)
#pragma unroll
        for (int j = 0; j < 4; j++) acc2[i][j] = 0.f;
    for (int v = 0; v < NVV; v++) {
        float a[4], s[4];
#pragma unroll
        for (int i = 0; i < 4; i++) a[i] = bufB[(h0 + 8 * i) * 132 + v];
#pragma unroll
        for (int j = 0; j < 4; j++) s[j] = supT[v * 129 + w0 + 32 * j];
#pragma unroll
        for (int i = 0; i < 4; i++)
#pragma unroll
            for (int j = 0; j < 4; j++) acc2[i][j] += a[i] * s[j];
    }

#pragma unroll
    for (int i = 0; i < 4; i++) {
#pragma unroll
        for (int j = 0; j < 4; j++) {
            int h = h0 + 8 * i, w = w0 + 32 * j;
            int n = h * NVV + w;
            float val = acc2[i][j];
            d_out[(long)b * (NHH * NTT) + (long)n * NTT + t] = val;
            gReprH[(long)r * NHH + n] = __float2half(val);
        }
    }
}

// ------------------------- pipelined gx GEMM (ST=3, 2 CTA/SM) --------------
__global__ void __launch_bounds__(256, 2) gemm_gx_kernel(const float* __restrict__ bias) {
    constexpr int BM = 128, BN = 128, BK = 64, ST = 3, LD = 72;
    extern __shared__ __half smh[];
    __half* As = smh;
    __half* Ws = smh + ST * BM * LD;

    int tid = threadIdx.x;
    int warp = tid >> 5, lane = tid & 31;
    int g = lane >> 2, ti = lane & 3;
    int wm = warp & 1, wn = warp >> 1;

    long rowA0 = (long)blockIdx.x * BM;
    long rowW0 = (long)blockIdx.y * BN;

    const __half* A = gReprH;
    const __half* W = gWih;

    int ldrow = tid >> 3, ldseg = tid & 7;
    uint64_t pol = mk_evict_last_policy();

    uint32_t aoff[4];
#pragma unroll
    for (int mt = 0; mt < 4; mt++)
        aoff[mt] = (wm * 64 + mt * 16 + (lane & 15)) * LD + (lane >> 4) * 8;
    uint32_t woff[2];
#pragma unroll
    for (int pr = 0; pr < 2; pr++)
        woff[pr] = (wn * 32 + pr * 16 + ((lane >> 4) & 1) * 8 + (lane & 7)) * LD
                   + ((lane >> 3) & 1) * 8;

    uint32_t As_base = smem_u32(As);
    uint32_t Ws_base = smem_u32(Ws);

#pragma unroll
    for (int s = 0; s < ST - 1; s++) {
        int k0 = s * BK;
#pragma unroll
        for (int i = 0; i < 4; i++) {
            int row = ldrow + i * 32;
            cp_async16_el(As + (s * BM + row) * LD + ldseg * 8,
                          A + (rowA0 + row) * (long)NHH + k0 + ldseg * 8, pol);
        }
#pragma unroll
        for (int i = 0; i < 4; i++) {
            int row = ldrow + i * 32;
            cp_async16(Ws + (s * BN + row) * LD + ldseg * 8,
                       W + (rowW0 + row) * (long)NHH + k0 + ldseg * 8);
        }
        cp_commit();
    }

    float acc[4][4][4];
#pragma unroll
    for (int mt = 0; mt < 4; mt++)
#pragma unroll
        for (int nt = 0; nt < 4; nt++)
#pragma unroll
            for (int q = 0; q < 4; q++) acc[mt][nt][q] = 0.f;

    const int KT = NHH / BK;
    for (int kt = 0; kt < KT; kt++) {
        cp_wait<ST - 2>();
        __syncthreads();
        if (kt + ST - 1 < KT) {
            int s = (kt + ST - 1) % ST;
            int k0 = (kt + ST - 1) * BK;
#pragma unroll
            for (int i = 0; i < 4; i++) {
                int row = ldrow + i * 32;
                cp_async16_el(As + (s * BM + row) * LD + ldseg * 8,
                              A + (rowA0 + row) * (long)NHH + k0 + ldseg * 8, pol);
            }
#pragma unroll
            for (int i = 0; i < 4; i++) {
                int row = ldrow + i * 32;
                cp_async16(Ws + (s * BN + row) * LD + ldseg * 8,
                           W + (rowW0 + row) * (long)NHH + k0 + ldseg * 8);
            }
        }
        cp_commit();  // every iter (tail alignment)

        uint32_t Ab = As_base + (uint32_t)((kt % ST) * BM * LD) * 2;
        uint32_t Wb = Ws_base + (uint32_t)((kt % ST) * BN * LD) * 2;

#pragma unroll
        for (int kk = 0; kk < BK; kk += 16) {
            uint32_t af[4][4];
#pragma unroll
            for (int mt = 0; mt < 4; mt++)
                ldsm_x4(af[mt][0], af[mt][1], af[mt][2], af[mt][3],
                        Ab + (aoff[mt] + kk) * 2);
            uint32_t bf[4][2];
#pragma unroll
            for (int pr = 0; pr < 2; pr++)
                ldsm_x4(bf[2 * pr][0], bf[2 * pr][1], bf[2 * pr + 1][0], bf[2 * pr + 1][1],
                        Wb + (woff[pr] + kk) * 2);
#pragma unroll
            for (int nt = 0; nt < 4; nt++)
#pragma unroll
                for (int mt = 0; mt < 4; mt++)
                    mma_m16n8k16(acc[mt][nt], af[mt], bf[nt][0], bf[nt][1]);
        }
    }

    float* C = gGx;
#pragma unroll
    for (int mt = 0; mt < 4; mt++) {
        long row = rowA0 + wm * 64 + mt * 16 + g;
#pragma unroll
        for (int nt = 0; nt < 4; nt++) {
            long col = rowW0 + wn * 32 + nt * 8 + 2 * ti;
            float bv0 = bias[col], bv1 = bias[col + 1];
            __stcs(&C[row * NH3 + col],           acc[mt][nt][0] + bv0);
            __stcs(&C[row * NH3 + col + 1],       acc[mt][nt][1] + bv1);
            __stcs(&C[(row + 8) * NH3 + col],     acc[mt][nt][2] + bv0);
            __stcs(&C[(row + 8) * NH3 + col + 1], acc[mt][nt][3] + bv1);
        }
    }
}

// ------------------------- persistent GRU (R13 best config) -----------------
// W: 6-stage TMA-bulk mbarrier ring (24KB tiles). A(h): 4-stage cp.async.
// States batched x4 timesteps in smem -> float4 coalesced stores.
__global__ void __launch_bounds__(256) gru_persistent_kernel(
    const float* __restrict__ h0,
    const float* __restrict__ b_hh,
    float* __restrict__ d_out) {
    constexpr int BK = 128, STA = 4, STW = 6, LDA = 136, AR = 32, KT = 32;
    constexpr int WTILE = 24576;
    extern __shared__ __align__(1024) char smraw[];
    __half* Ws   = (__half*)smraw;                       // 147456
    __half* As   = (__half*)(smraw + 147456);            // 34816
    float*  gh_s = (float*)(smraw + 182272);             // 12800
    uint32_t wbar0 = smem_u32(smraw + 195072);           // 6 x 8B (+pad 64)
    float*  sbuf = (float*)(smraw + 195136);             // 16384

    int tid = threadIdx.x;
    int warp = tid >> 5, lane = tid & 31;
    int g = lane >> 2, ti = lane & 3;
    int wm = warp & 1, wn = warp >> 1;
    int n0 = blockIdx.x * 32;
    int ldrow = tid >> 4, ldseg = tid & 15;

    uint32_t aoff = (wm * 16 + (lane & 15)) * LDA + (lane >> 4) * 8;
    int row4 = wn * 24 + ((lane >> 4) & 1) * 8 + (lane & 7);
    uint32_t wbase4 = (uint32_t)((row4 >> 5) * 8192 + (row4 & 31) * 128);
    uint32_t swz4   = (uint32_t)(((row4 & 31) & 7) << 4);
    uint32_t cb4    = ((lane >> 3) & 1) * 16;
    int row2 = wn * 24 + 16 + (lane & 7);
    uint32_t wbase2 = (uint32_t)((row2 >> 5) * 8192 + (row2 & 31) * 128);
    uint32_t swz2   = (uint32_t)(((row2 & 31) & 7) << 4);
    uint32_t cb2    = ((lane >> 3) & 1) * 16;

    uint32_t As_base = smem_u32(As);
    uint32_t Ws_base = smem_u32(Ws);

    long aoffg[2];
#pragma unroll
    for (int j = 0; j < 2; j++) aoffg[j] = (long)(ldrow + j * 16) * NHH + ldseg * 8;

    int pb[4], pn[4];
    float hreg[4], bhr[4], bhz[4], bhn[4];
#pragma unroll
    for (int i = 0; i < 4; i++) {
        int idx = tid + i * 256;
        pb[i] = idx >> 5;
        pn[i] = n0 + (idx & 31);
        hreg[i] = h0[pn[i]];
        bhr[i] = b_hh[pn[i]];
        bhz[i] = b_hh[NHH + pn[i]];
        bhn[i] = b_hh[2 * NHH + pn[i]];
    }

    unsigned barBase = *(volatile unsigned*)&gBarPhase;
    const __half* wsrc = gWhh + (long)blockIdx.x * KT * 12288;

    if (tid == 0) {
        for (int s = 0; s < STW; s++) mbar_init(wbar0 + 8 * s, 1);
    }
    __syncthreads();
    asm volatile("fence.proxy.async.shared::cta;" ::: "memory");

    if (tid == 0) {
#pragma unroll
        for (int s = 0; s < STW - 1; s++) {
            mbar_expect_tx(wbar0 + 8 * s, WTILE);
            tma_bulk_1d(Ws_base + s * WTILE, wsrc + (long)s * 12288, WTILE,
                        wbar0 + 8 * s);
        }
    }
    {
        const __half* A0 = gHh[0];
#pragma unroll
        for (int s = 0; s < STA - 1; s++) {
#pragma unroll
            for (int j = 0; j < 2; j++)
                cp_async16(As + (s * AR + ldrow + j * 16) * LDA + ldseg * 8,
                           A0 + aoffg[j] + s * BK);
            cp_commit();
        }
    }

    int cs = 0, cph = 0;
    int si = STW - 1;

    for (int t = 0; t < NTT; t++) {
        const __half* Ain = gHh[t & 1];
        __half* Aout = gHh[(t + 1) & 1];

        float pxr[4], pxz[4], pxn[4];
#pragma unroll
        for (int i = 0; i < 4; i++) {
            long gxr = ((long)(t * NB + pb[i])) * NH3 + pn[i];
            pxr[i] = __ldcs(&gGx[gxr]);
            pxz[i] = __ldcs(&gGx[gxr + NHH]);
            pxn[i] = __ldcs(&gGx[gxr + 2 * NHH]);
        }

        float acc[3][4];
#pragma unroll
        for (int nt = 0; nt < 3; nt++)
#pragma unroll
            for (int q = 0; q < 4; q++) acc[nt][q] = 0.f;

        for (int kt = 0; kt < KT; kt++) {
            mbar_wait_parity(wbar0 + 8 * cs, (uint32_t)cph);
            cp_wait<STA - 2>();
            __syncthreads();

            if (t < NTT - 1 || kt < KT - (STW - 1)) {
                if (tid == 0) {
                    int ktn = kt + (STW - 1);
                    if (ktn >= KT) ktn -= KT;
                    mbar_expect_tx(wbar0 + 8 * si, WTILE);
                    tma_bulk_1d(Ws_base + si * WTILE, wsrc + (long)ktn * 12288,
                                WTILE, wbar0 + 8 * si);
                }
                si++; if (si == STW) si = 0;
            }
            if (kt + STA - 1 < KT) {
                int s = (kt + STA - 1) & 3;
                int k0 = (kt + STA - 1) * BK;
#pragma unroll
                for (int j = 0; j < 2; j++)
                    cp_async16(As + (s * AR + ldrow + j * 16) * LDA + ldseg * 8,
                               Ain + aoffg[j] + k0);
            }
            cp_commit();

            uint32_t Ab = As_base + (uint32_t)((kt & 3) * AR * LDA) * 2;
            uint32_t Wb = Ws_base + (uint32_t)(cs * WTILE);

#pragma unroll
            for (int kk = 0; kk < BK; kk += 16) {
                uint32_t af[4];
                ldsm_x4(af[0], af[1], af[2], af[3], Ab + (aoff + kk) * 2);
                uint32_t khb = (uint32_t)((kk >> 6) * 4096);
                uint32_t klb = (uint32_t)((kk & 63) * 2);
                uint32_t b00, b01, b10, b11, b20, b21;
                ldsm_x4(b00, b01, b10, b11,
                        Wb + wbase4 + khb + ((cb4 + klb) ^ swz4));
                ldsm_x2(b20, b21,
                        Wb + wbase2 + khb + ((cb2 + klb) ^ swz2));
                mma_m16n8k16(acc[0], af, b00, b01);
                mma_m16n8k16(acc[1], af, b10, b11);
                mma_m16n8k16(acc[2], af, b20, b21);
            }
            cs++; if (cs == STW) { cs = 0; cph ^= 1; }
        }

#pragma unroll
        for (int nt = 0; nt < 3; nt++) {
            int c = (wn * 3 + nt) * 8 + 2 * ti;
            int m = wm * 16 + g;
            gh_s[m * 100 + c]           = acc[nt][0];
            gh_s[m * 100 + c + 1]       = acc[nt][1];
            gh_s[(m + 8) * 100 + c]     = acc[nt][2];
            gh_s[(m + 8) * 100 + c + 1] = acc[nt][3];
        }
        __syncthreads();

        int tph = t & 3;
#pragma unroll
        for (int i = 0; i < 4; i++) {
            int idx = tid + i * 256;
            int b = pb[i], nl = pn[i] - n0, n = pn[i];

            float hr = gh_s[b * 100 + nl]      + bhr[i];
            float hz = gh_s[b * 100 + 32 + nl] + bhz[i];
            float hn = gh_s[b * 100 + 64 + nl] + bhn[i];

            float r = 1.f / (1.f + expf(-(pxr[i] + hr)));
            float z = 1.f / (1.f + expf(-(pxz[i] + hz)));
            float nn = tanhf(pxn[i] + r * hn);
            float hnew = (1.f - z) * nn + z * hreg[i];
            hreg[i] = hnew;

            Aout[b * NHH + n] = __float2half(hnew);
            sbuf[tph * 1024 + idx] = hnew;
            if (t == NTT - 1) d_out[OUT_HENC + b * NHH + n] = hnew;
        }

        if (tph == 3) {
#pragma unroll
            for (int i = 0; i < 4; i++) {
                int idx = tid + i * 256;
                int b = pb[i], n = pn[i];
                float4 v = make_float4(sbuf[idx], sbuf[1024 + idx],
                                       sbuf[2048 + idx], sbuf[3072 + idx]);
                __stcs((float4*)&d_out[OUT_STATES + (long)b * (NHH * NTT)
                                       + (long)n * NTT + (t - 3)], v);
            }
        }

        if (t < NTT - 1) {
            __syncthreads();
            if (tid == 0) {
                __threadfence();
                unsigned arrived = atomicAdd(&gBarCnt, 1u);
                unsigned target = barBase + (unsigned)(t + 1);
                if (arrived == NBLK - 1) {
                    gBarCnt = 0;
                    __threadfence();
                    atomicExch(&gBarPhase, target);
                } else {
                    while ((int)(atomicAdd(&gBarPhase, 0u) - target) < 0) {
                        __nanosleep(32);
                    }
                }
            }
            __syncthreads();

            const __half* A2 = gHh[(t + 1) & 1];
#pragma unroll
            for (int s = 0; s < STA - 1; s++) {
#pragma unroll
                for (int j = 0; j < 2; j++)
                    cp_async16(As + (s * AR + ldrow + j * 16) * LDA + ldseg * 8,
                               A2 + aoffg[j] + s * BK);
                cp_commit();
            }
        }
    }
    cp_wait<0>();
}

// ------------------------- classifier ---------------------------------------
__global__ void classifier_kernel(const float* __restrict__ w1, const float* __restrict__ b1,
                                  const float* __restrict__ w2, const float* __restrict__ b2,
                                  float* __restrict__ d_out) {
    __shared__ float hid[300];
    int b = blockIdx.x;
    int tid = threadIdx.x, warp = tid >> 5, lane = tid & 31;
    const float* hb = d_out + OUT_HENC + (long)b * NHH;

    for (int j = warp; j < 300; j += 8) {
        float s = 0.f;
        for (int k = lane; k < NHH; k += 32) s += hb[k] * w1[(long)j * NHH + k];
#pragma unroll
        for (int off = 16; off; off >>= 1) s += __shfl_xor_sync(0xffffffffu, s, off);
        if (lane == 0) hid[j] = fmaxf(s + b1[j], 0.f);
    }
    __syncthreads();
    if (warp < 2) {
        float s = 0.f;
        for (int j = lane; j < 300; j += 32) s += hid[j] * w2[warp * 300 + j];
#pragma unroll
        for (int off = 16; off; off >>= 1) s += __shfl_xor_sync(0xffffffffu, s, off);
        if (lane == 0) d_out[OUT_CLS + b * 2 + warp] = s + b2[warp];
    }
}

// ------------------------- launch --------------------------------------------
extern "C" void kernel_launch(void* const* d_in, const int* in_sizes, int n_in,
                              void* d_out, int out_size) {
    const float* x      = (const float*)d_in[0];
    const float* adj    = (const float*)d_in[1];
    const float* h0     = (const float*)d_in[3];
    const float* conv_w = (const float*)d_in[4];
    const float* conv_b = (const float*)d_in[5];
    const float* w_ih   = (const float*)d_in[6];
    const float* w_hh   = (const float*)d_in[7];
    const float* b_ih   = (const float*)d_in[8];
    const float* b_hh   = (const float*)d_in[9];
    const float* cls_w1 = (const float*)d_in[10];
    const float* cls_b1 = (const float*)d_in[11];
    const float* cls_w2 = (const float*)d_in[12];
    const float* cls_b2 = (const float*)d_in[13];
    float* out = (float*)d_out;

    const int REPR_SMEM = (128 * 129 + 32 * 132 + 32 * 132 + 12 * 128) * 4;  // 105984
    const int GX_SMEM   = 3 * (128 + 128) * 72 * 2;                          // 110592
    const int PS_SMEM   = 195136 + 16384;                                    // 211520
    cudaFuncSetAttribute(repr_kernel, cudaFuncAttributeMaxDynamicSharedMemorySize, REPR_SMEM);
    cudaFuncSetAttribute(gemm_gx_kernel, cudaFuncAttributeMaxDynamicSharedMemorySize, GX_SMEM);
    cudaFuncSetAttribute(gru_persistent_kernel, cudaFuncAttributeMaxDynamicSharedMemorySize, PS_SMEM);

    // Launch order: repr at index 3 (the ncu capture slot) this round.
    support_kernel<<<1, 128>>>(adj);
    wih_convert_kernel<<<2048, 256>>>((const float4*)w_ih);
    init_whh_kernel<<<12288, 256>>>(w_hh, h0);
    repr_kernel<<<NR, 256, REPR_SMEM>>>(x, conv_w, conv_b, out);
    gemm_gx_kernel<<<dim3(25, 96), 256, GX_SMEM>>>(b_ih);
    gru_persistent_kernel<<<NBLK, 256, PS_SMEM>>>(h0, b_hh, out);
    classifier_kernel<<<NB, 256>>>(cls_w1, cls_b1, cls_w2, cls_b2, out);
}

// round 17
// speedup vs baseline: 1.0189x; 1.0076x over previous
#include <cuda_runtime.h>
#include <cuda_fp16.h>
#include <cstdint>
#include <math.h>

// Problem dims
#define NB   32
#define NI   12
#define NVV  128
#define NHD  32
#define NTT  100
#define NHH  4096
#define NH3  12288
#define NR   3200
#define NBLK 128

// d_out region offsets (floats)
static const long OUT_STATES = 13107200L;
static const long OUT_HENC   = 26214400L;
static const long OUT_CLS    = 26345472L;

// ------------------------- scratch -----------------------------------------
__device__ float    gSupportT[NVV * NVV];        // transposed: [v][w]
__device__ __align__(256) __half gReprH[(long)NR * NHH];
__device__ __align__(256) __half gWih[(long)NH3 * NHH];
// W_hh block-tiled + SW128-swizzled (see init_whh_kernel)
__device__ __align__(256) __half gWhh[(long)NH3 * NHH];
__device__ __align__(256) float  gGx[(long)NR * NH3];
__device__ __align__(256) __half gHh[2][NB * NHH];
__device__ unsigned gBarCnt;
__device__ unsigned gBarPhase;

// ------------------------- asm helpers -------------------------------------
__device__ __forceinline__ uint64_t mk_evict_last_policy() {
    uint64_t pol;
    asm("createpolicy.fractional.L2::evict_last.b64 %0, 1.0;" : "=l"(pol));
    return pol;
}
__device__ __forceinline__ void cp_async16(void* smem, const void* gmem) {
    uint32_t s = (uint32_t)__cvta_generic_to_shared(smem);
    asm volatile("cp.async.cg.shared.global [%0], [%1], 16;\n" :: "r"(s), "l"(gmem));
}
__device__ __forceinline__ void cp_async16_el(void* smem, const void* gmem, uint64_t pol) {
    uint32_t s = (uint32_t)__cvta_generic_to_shared(smem);
    asm volatile("cp.async.cg.shared.global.L2::cache_hint [%0], [%1], 16, %2;\n"
                 :: "r"(s), "l"(gmem), "l"(pol));
}
__device__ __forceinline__ void cp_commit() {
    asm volatile("cp.async.commit_group;\n");
}
template <int N>
__device__ __forceinline__ void cp_wait() {
    asm volatile("cp.async.wait_group %0;\n" :: "n"(N));
}
__device__ __forceinline__ uint32_t smem_u32(const void* p) {
    return (uint32_t)__cvta_generic_to_shared(p);
}
__device__ __forceinline__ void ldsm_x4(uint32_t& r0, uint32_t& r1, uint32_t& r2,
                                        uint32_t& r3, uint32_t addr) {
    asm volatile("ldmatrix.sync.aligned.m8n8.x4.shared.b16 {%0,%1,%2,%3}, [%4];\n"
                 : "=r"(r0), "=r"(r1), "=r"(r2), "=r"(r3) : "r"(addr));
}
__device__ __forceinline__ void ldsm_x2(uint32_t& r0, uint32_t& r1, uint32_t addr) {
    asm volatile("ldmatrix.sync.aligned.m8n8.x2.shared.b16 {%0,%1}, [%2];\n"
                 : "=r"(r0), "=r"(r1) : "r"(addr));
}
__device__ __forceinline__ void mma_m16n8k16(float* d, const uint32_t* a,
                                             uint32_t b0, uint32_t b1) {
    asm volatile(
        "mma.sync.aligned.m16n8k16.row.col.f32.f16.f16.f32 "
        "{%0,%1,%2,%3}, {%4,%5,%6,%7}, {%8,%9}, {%0,%1,%2,%3};\n"
        : "+f"(d[0]), "+f"(d[1]), "+f"(d[2]), "+f"(d[3])
        : "r"(a[0]), "r"(a[1]), "r"(a[2]), "r"(a[3]), "r"(b0), "r"(b1));
}
__device__ __forceinline__ void mbar_init(uint32_t addr, uint32_t cnt) {
    asm volatile("mbarrier.init.shared.b64 [%0], %1;" :: "r"(addr), "r"(cnt) : "memory");
}
__device__ __forceinline__ void mbar_expect_tx(uint32_t addr, uint32_t bytes) {
    asm volatile("mbarrier.arrive.expect_tx.shared.b64 _, [%0], %1;"
                 :: "r"(addr), "r"(bytes) : "memory");
}
__device__ __forceinline__ void mbar_wait_parity(uint32_t addr, uint32_t parity) {
    uint32_t done;
    asm volatile(
        "{\n\t.reg .pred p;\n\t"
        "mbarrier.try_wait.parity.acquire.cta.shared::cta.b64 p, [%1], %2;\n\t"
        "selp.b32 %0, 1, 0, p;\n\t}"
        : "=r"(done) : "r"(addr), "r"(parity) : "memory");
    if (!done) {
        asm volatile(
            "{\n\t.reg .pred P1;\n\t"
            "WAIT_LOOP_%=:\n\t"
            "mbarrier.try_wait.parity.acquire.cta.shared::cta.b64 P1, [%0], %1, 0x989680;\n\t"
            "@P1 bra.uni WAIT_DONE_%=;\n\t"
            "bra.uni WAIT_LOOP_%=;\n\t"
            "WAIT_DONE_%=:\n\t}"
            :: "r"(addr), "r"(parity) : "memory");
    }
}
__device__ __forceinline__ void tma_bulk_1d(uint32_t smem_dst, const void* gsrc,
                                            uint32_t bytes, uint32_t mbar) {
    asm volatile(
        "cp.async.bulk.shared::cluster.global.mbarrier::complete_tx::bytes "
        "[%0], [%1], %2, [%3];"
        :: "r"(smem_dst), "l"(gsrc), "r"(bytes), "r"(mbar) : "memory");
}

// ------------------------- support (transposed) ------------------------------
__global__ void support_kernel(const float* __restrict__ adj) {
    int w = threadIdx.x;  // 128 threads
    float s = 0.f;
    for (int v = 0; v < NVV; v++) s += adj[w * NVV + v];
    float inv = 1.f / (s + 1e-6f);
    for (int v = 0; v < NVV; v++) gSupportT[v * NVV + w] = adj[w * NVV + v] * inv;
}

// ------------------------- W_ih convert --------------------------------------
__global__ void wih_convert_kernel(const float4* __restrict__ wih4) {
    long gid = (long)blockIdx.x * blockDim.x + threadIdx.x;
    long stride = (long)gridDim.x * blockDim.x;
    long n4 = (long)NH3 * NHH / 4;
    __half2* wih_o = (__half2*)gWih;
    for (long i = gid; i < n4; i += stride) {
        float4 a = wih4[i];
        wih_o[2 * i]     = __floats2half2_rn(a.x, a.y);
        wih_o[2 * i + 1] = __floats2half2_rn(a.z, a.w);
    }
}

// ------------------------- W_hh tiler (coalesced) + h0 init ----------------
__global__ void __launch_bounds__(256) init_whh_kernel(const float* __restrict__ whh,
                                                       const float* __restrict__ h0) {
    __shared__ __half sh[32 * 128];   // 8KB tile (fp16)
    int tid = threadIdx.x;
    int bid = blockIdx.x;             // 12288 blocks

    long gid = (long)bid * 256 + tid;
    if (gid < (long)NB * NHH) gHh[0][gid] = __float2half(h0[gid & (NHH - 1)]);

    int gate = bid % 3;
    int kt   = (bid / 3) % 32;
    int j    = bid / 96;

    {
        int row = tid >> 3;
        int c0  = (tid & 7) * 16;
        const float4* src = (const float4*)(whh +
            ((long)gate * NHH + j * 32 + row) * (long)NHH + kt * 128 + c0);
        __half2* sp = (__half2*)(sh + row * 128 + c0);
        float4 v;
        v = src[0]; sp[0] = __floats2half2_rn(v.x, v.y); sp[1] = __floats2half2_rn(v.z, v.w);
        v = src[1]; sp[2] = __floats2half2_rn(v.x, v.y); sp[3] = __floats2half2_rn(v.z, v.w);
        v = src[2]; sp[4] = __floats2half2_rn(v.x, v.y); sp[5] = __floats2half2_rn(v.z, v.w);
        v = src[3]; sp[6] = __floats2half2_rn(v.x, v.y); sp[7] = __floats2half2_rn(v.z, v.w);
    }
    __syncthreads();

#pragma unroll
    for (int w = 0; w < 2; w++) {
        int s = tid + w * 256;
        int khalf = s >> 8;
        int qoff  = (s & 255) * 16;
        int l = qoff ^ ((qoff >> 3) & 0x70);
        int r = l >> 7;
        int cl = (l & 127) >> 1;
        uint4 val = *(const uint4*)(sh + r * 128 + khalf * 64 + cl);
        *(uint4*)((char*)gWhh + (long)bid * 8192 + khalf * 4096 + qoff) = val;
    }
}

// ------------------------- repr (phase-optimized) ----------------------------
// Per warp per v: 1 broadcast LDS.128 (A) + 1 LDS.128 (support) = 5 phases
// vs 8 scalar loads / 8 phases before. Same products, same v-order ->
// bit-identical results.
__global__ void __launch_bounds__(256) repr_kernel(const float* __restrict__ x,
                                                   const float* __restrict__ conv_w,
                                                   const float* __restrict__ conv_b,
                                                   float* __restrict__ d_out) {
    extern __shared__ float sm[];
    float* supT  = sm;                    // [128 v][132]
    float* bufAT = supT + 128 * 132;      // [128 v][32]  slot(h) interleave
    float* bufBT = bufAT + 128 * 32;      // [128 v][32]  rotated slots
    float* xs    = bufBT + 128 * 32;      // [12][128]

    int r = blockIdx.x;
    int t = r >> 5;
    int b = r & 31;
    int tid = threadIdx.x;
    int lane = tid & 31;
    int h0 = tid >> 5;    // warp id; also h-base selector for the 4x4 tile

    // conv weights for h = lane (fixed per thread) into registers
    float cw[NI];
#pragma unroll
    for (int i = 0; i < NI; i++) cw[i] = conv_w[lane * NI + i];
    float cb = conv_b[lane];

    // stage supT (coalesced read, conflict-free store: consecutive w)
    for (int idx = tid; idx < NVV * NVV; idx += 256) {
        supT[(idx >> 7) * 132 + (idx & 127)] = gSupportT[idx];
    }
    // stage x slice
    for (int idx = tid; idx < NI * NVV; idx += 256) {
        int i = idx >> 7, v = idx & 127;
        xs[i * 128 + v] = x[(((long)b * NI + i) * NVV + v) * NTT + t];
    }
    __syncthreads();

    // conv: thread computes x_in[h=lane][v] for v = h0 + 8k
    // store slot(h) = (h&7)*4 + (h>>3): permutation -> conflict-free
    int slot = (lane & 7) * 4 + (lane >> 3);
#pragma unroll
    for (int k = 0; k < 16; k++) {
        int v = h0 + k * 8;
        float a = cb;
#pragma unroll
        for (int i = 0; i < NI; i++) a += cw[i] * xs[i * 128 + v];
        bufAT[v * 32 + slot] = a;
    }
    __syncthreads();

    // pass 1: x1 = x_in @ supT ; thread tile h = h0+8i, w = lane*4+j
    float acc1[4][4];
#pragma unroll
    for (int i = 0; i < 4; i++)
#pragma unroll
        for (int j = 0; j < 4; j++) acc1[i][j] = 0.f;
    for (int v = 0; v < NVV; v++) {
        float4 a4 = *(const float4*)&bufAT[v * 32 + h0 * 4];   // broadcast
        float4 s4 = *(const float4*)&supT[v * 132 + lane * 4];
        float av[4] = {a4.x, a4.y, a4.z, a4.w};
        float sv[4] = {s4.x, s4.y, s4.z, s4.w};
#pragma unroll
        for (int i = 0; i < 4; i++)
#pragma unroll
            for (int j = 0; j < 4; j++) acc1[i][j] += av[i] * sv[j];
    }

    // store x1 transposed with rotation swizzle (4-phase float4 stores)
#pragma unroll
    for (int j = 0; j < 4; j++) {
        int w = lane * 4 + j;
        int rs = ((h0 + ((w >> 3) & 7)) & 7) * 4;
        *(float4*)&bufBT[w * 32 + rs] =
            make_float4(acc1[0][j], acc1[1][j], acc1[2][j], acc1[3][j]);
    }
    __syncthreads();

    // pass 2: x2 = x1 @ supT
    float acc2[4][4];
#pragma unroll
    for (int i = 0; i < 4; i++)
#pragma unroll
        for (int j = 0; j < 4; j++) acc2[i][j] = 0.f;
    for (int v = 0; v < NVV; v++) {
        int rs = ((h0 + ((v >> 3) & 7)) & 7) * 4;
        float4 a4 = *(const float4*)&bufBT[v * 32 + rs];       // broadcast
        float4 s4 = *(const float4*)&supT[v * 132 + lane * 4];
        float av[4] = {a4.x, a4.y, a4.z, a4.w};
        float sv[4] = {s4.x, s4.y, s4.z, s4.w};
#pragma unroll
        for (int i = 0; i < 4; i++)
#pragma unroll
            for (int j = 0; j < 4; j++) acc2[i][j] += av[i] * sv[j];
    }

    // outputs: n = (h0+8i)*128 + lane*4 + j
#pragma unroll
    for (int i = 0; i < 4; i++) {
        int h = h0 + 8 * i;
        int nbase = h * NVV + lane * 4;
#pragma unroll
        for (int j = 0; j < 4; j++)
            d_out[(long)b * (NHH * NTT) + (long)(nbase + j) * NTT + t] = acc2[i][j];
        __half2 p0 = __floats2half2_rn(acc2[i][0], acc2[i][1]);
        __half2 p1 = __floats2half2_rn(acc2[i][2], acc2[i][3]);
        *(__half2*)&gReprH[(long)r * NHH + nbase]     = p0;
        *(__half2*)&gReprH[(long)r * NHH + nbase + 2] = p1;
    }
}

// ------------------------- pipelined gx GEMM (ST=3, 2 CTA/SM) --------------
__global__ void __launch_bounds__(256, 2) gemm_gx_kernel(const float* __restrict__ bias) {
    constexpr int BM = 128, BN = 128, BK = 64, ST = 3, LD = 72;
    extern __shared__ __half smh[];
    __half* As = smh;
    __half* Ws = smh + ST * BM * LD;

    int tid = threadIdx.x;
    int warp = tid >> 5, lane = tid & 31;
    int g = lane >> 2, ti = lane & 3;
    int wm = warp & 1, wn = warp >> 1;

    long rowA0 = (long)blockIdx.x * BM;
    long rowW0 = (long)blockIdx.y * BN;

    const __half* A = gReprH;
    const __half* W = gWih;

    int ldrow = tid >> 3, ldseg = tid & 7;
    uint64_t pol = mk_evict_last_policy();

    uint32_t aoff[4];
#pragma unroll
    for (int mt = 0; mt < 4; mt++)
        aoff[mt] = (wm * 64 + mt * 16 + (lane & 15)) * LD + (lane >> 4) * 8;
    uint32_t woff[2];
#pragma unroll
    for (int pr = 0; pr < 2; pr++)
        woff[pr] = (wn * 32 + pr * 16 + ((lane >> 4) & 1) * 8 + (lane & 7)) * LD
                   + ((lane >> 3) & 1) * 8;

    uint32_t As_base = smem_u32(As);
    uint32_t Ws_base = smem_u32(Ws);

#pragma unroll
    for (int s = 0; s < ST - 1; s++) {
        int k0 = s * BK;
#pragma unroll
        for (int i = 0; i < 4; i++) {
            int row = ldrow + i * 32;
            cp_async16_el(As + (s * BM + row) * LD + ldseg * 8,
                          A + (rowA0 + row) * (long)NHH + k0 + ldseg * 8, pol);
        }
#pragma unroll
        for (int i = 0; i < 4; i++) {
            int row = ldrow + i * 32;
            cp_async16(Ws + (s * BN + row) * LD + ldseg * 8,
                       W + (rowW0 + row) * (long)NHH + k0 + ldseg * 8);
        }
        cp_commit();
    }

    float acc[4][4][4];
#pragma unroll
    for (int mt = 0; mt < 4; mt++)
#pragma unroll
        for (int nt = 0; nt < 4; nt++)
#pragma unroll
            for (int q = 0; q < 4; q++) acc[mt][nt][q] = 0.f;

    const int KT = NHH / BK;
    for (int kt = 0; kt < KT; kt++) {
        cp_wait<ST - 2>();
        __syncthreads();
        if (kt + ST - 1 < KT) {
            int s = (kt + ST - 1) % ST;
            int k0 = (kt + ST - 1) * BK;
#pragma unroll
            for (int i = 0; i < 4; i++) {
                int row = ldrow + i * 32;
                cp_async16_el(As + (s * BM + row) * LD + ldseg * 8,
                              A + (rowA0 + row) * (long)NHH + k0 + ldseg * 8, pol);
            }
#pragma unroll
            for (int i = 0; i < 4; i++) {
                int row = ldrow + i * 32;
                cp_async16(Ws + (s * BN + row) * LD + ldseg * 8,
                           W + (rowW0 + row) * (long)NHH + k0 + ldseg * 8);
            }
        }
        cp_commit();  // every iter (tail alignment)

        uint32_t Ab = As_base + (uint32_t)((kt % ST) * BM * LD) * 2;
        uint32_t Wb = Ws_base + (uint32_t)((kt % ST) * BN * LD) * 2;

#pragma unroll
        for (int kk = 0; kk < BK; kk += 16) {
            uint32_t af[4][4];
#pragma unroll
            for (int mt = 0; mt < 4; mt++)
                ldsm_x4(af[mt][0], af[mt][1], af[mt][2], af[mt][3],
                        Ab + (aoff[mt] + kk) * 2);
            uint32_t bf[4][2];
#pragma unroll
            for (int pr = 0; pr < 2; pr++)
                ldsm_x4(bf[2 * pr][0], bf[2 * pr][1], bf[2 * pr + 1][0], bf[2 * pr + 1][1],
                        Wb + (woff[pr] + kk) * 2);
#pragma unroll
            for (int nt = 0; nt < 4; nt++)
#pragma unroll
                for (int mt = 0; mt < 4; mt++)
                    mma_m16n8k16(acc[mt][nt], af[mt], bf[nt][0], bf[nt][1]);
        }
    }

    float* C = gGx;
#pragma unroll
    for (int mt = 0; mt < 4; mt++) {
        long row = rowA0 + wm * 64 + mt * 16 + g;
#pragma unroll
        for (int nt = 0; nt < 4; nt++) {
            long col = rowW0 + wn * 32 + nt * 8 + 2 * ti;
            float bv0 = bias[col], bv1 = bias[col + 1];
            __stcs(&C[row * NH3 + col],           acc[mt][nt][0] + bv0);
            __stcs(&C[row * NH3 + col + 1],       acc[mt][nt][1] + bv1);
            __stcs(&C[(row + 8) * NH3 + col],     acc[mt][nt][2] + bv0);
            __stcs(&C[(row + 8) * NH3 + col + 1], acc[mt][nt][3] + bv1);
        }
    }
}

// ------------------------- persistent GRU (barrier-overlapped epilogue) -----
// W: 6-stage TMA-bulk mbarrier ring (24KB tiles). A(h): 4-stage cp.async.
// States flush + next-step gGx prefetch overlap the grid-barrier wait.
__global__ void __launch_bounds__(256) gru_persistent_kernel(
    const float* __restrict__ h0,
    const float* __restrict__ b_hh,
    float* __restrict__ d_out) {
    constexpr int BK = 128, STA = 4, STW = 6, LDA = 136, AR = 32, KT = 32;
    constexpr int WTILE = 24576;
    extern __shared__ __align__(1024) char smraw[];
    __half* Ws   = (__half*)smraw;                       // 147456
    __half* As   = (__half*)(smraw + 147456);            // 34816
    float*  gh_s = (float*)(smraw + 182272);             // 12800
    uint32_t wbar0 = smem_u32(smraw + 195072);           // 6 x 8B (+pad 64)
    float*  sbuf = (float*)(smraw + 195136);             // 16384

    int tid = threadIdx.x;
    int warp = tid >> 5, lane = tid & 31;
    int g = lane >> 2, ti = lane & 3;
    int wm = warp & 1, wn = warp >> 1;
    int n0 = blockIdx.x * 32;
    int ldrow = tid >> 4, ldseg = tid & 15;

    uint32_t aoff = (wm * 16 + (lane & 15)) * LDA + (lane >> 4) * 8;
    int row4 = wn * 24 + ((lane >> 4) & 1) * 8 + (lane & 7);
    uint32_t wbase4 = (uint32_t)((row4 >> 5) * 8192 + (row4 & 31) * 128);
    uint32_t swz4   = (uint32_t)(((row4 & 31) & 7) << 4);
    uint32_t cb4    = ((lane >> 3) & 1) * 16;
    int row2 = wn * 24 + 16 + (lane & 7);
    uint32_t wbase2 = (uint32_t)((row2 >> 5) * 8192 + (row2 & 31) * 128);
    uint32_t swz2   = (uint32_t)(((row2 & 31) & 7) << 4);
    uint32_t cb2    = ((lane >> 3) & 1) * 16;

    uint32_t As_base = smem_u32(As);
    uint32_t Ws_base = smem_u32(Ws);

    long aoffg[2];
#pragma unroll
    for (int j = 0; j < 2; j++) aoffg[j] = (long)(ldrow + j * 16) * NHH + ldseg * 8;

    int pb[4], pn[4];
    float hreg[4], bhr[4], bhz[4], bhn[4];
#pragma unroll
    for (int i = 0; i < 4; i++) {
        int idx = tid + i * 256;
        pb[i] = idx >> 5;
        pn[i] = n0 + (idx & 31);
        hreg[i] = h0[pn[i]];
        bhr[i] = b_hh[pn[i]];
        bhz[i] = b_hh[NHH + pn[i]];
        bhn[i] = b_hh[2 * NHH + pn[i]];
    }

    unsigned barBase = *(volatile unsigned*)&gBarPhase;
    const __half* wsrc = gWhh + (long)blockIdx.x * KT * 12288;

    if (tid == 0) {
        for (int s = 0; s < STW; s++) mbar_init(wbar0 + 8 * s, 1);
    }
    __syncthreads();
    asm volatile("fence.proxy.async.shared::cta;" ::: "memory");

    if (tid == 0) {
#pragma unroll
        for (int s = 0; s < STW - 1; s++) {
            mbar_expect_tx(wbar0 + 8 * s, WTILE);
            tma_bulk_1d(Ws_base + s * WTILE, wsrc + (long)s * 12288, WTILE,
                        wbar0 + 8 * s);
        }
    }
    {
        const __half* A0 = gHh[0];
#pragma unroll
        for (int s = 0; s < STA - 1; s++) {
#pragma unroll
            for (int j = 0; j < 2; j++)
                cp_async16(As + (s * AR + ldrow + j * 16) * LDA + ldseg * 8,
                           A0 + aoffg[j] + s * BK);
            cp_commit();
        }
    }

    int cs = 0, cph = 0;
    int si = STW - 1;

    // prefetch gx for t=0
    float pxr[4], pxz[4], pxn[4];
#pragma unroll
    for (int i = 0; i < 4; i++) {
        long gxr = ((long)(0 * NB + pb[i])) * NH3 + pn[i];
        pxr[i] = __ldcs(&gGx[gxr]);
        pxz[i] = __ldcs(&gGx[gxr + NHH]);
        pxn[i] = __ldcs(&gGx[gxr + 2 * NHH]);
    }

    for (int t = 0; t < NTT; t++) {
        const __half* Ain = gHh[t & 1];
        __half* Aout = gHh[(t + 1) & 1];

        float acc[3][4];
#pragma unroll
        for (int nt = 0; nt < 3; nt++)
#pragma unroll
            for (int q = 0; q < 4; q++) acc[nt][q] = 0.f;

        for (int kt = 0; kt < KT; kt++) {
            mbar_wait_parity(wbar0 + 8 * cs, (uint32_t)cph);
            cp_wait<STA - 2>();
            __syncthreads();

            if (t < NTT - 1 || kt < KT - (STW - 1)) {
                if (tid == 0) {
                    int ktn = kt + (STW - 1);
                    if (ktn >= KT) ktn -= KT;
                    mbar_expect_tx(wbar0 + 8 * si, WTILE);
                    tma_bulk_1d(Ws_base + si * WTILE, wsrc + (long)ktn * 12288,
                                WTILE, wbar0 + 8 * si);
                }
                si++; if (si == STW) si = 0;
            }
            if (kt + STA - 1 < KT) {
                int s = (kt + STA - 1) & 3;
                int k0 = (kt + STA - 1) * BK;
#pragma unroll
                for (int j = 0; j < 2; j++)
                    cp_async16(As + (s * AR + ldrow + j * 16) * LDA + ldseg * 8,
                               Ain + aoffg[j] + k0);
            }
            cp_commit();

            uint32_t Ab = As_base + (uint32_t)((kt & 3) * AR * LDA) * 2;
            uint32_t Wb = Ws_base + (uint32_t)(cs * WTILE);

#pragma unroll
            for (int kk = 0; kk < BK; kk += 16) {
                uint32_t af[4];
                ldsm_x4(af[0], af[1], af[2], af[3], Ab + (aoff + kk) * 2);
                uint32_t khb = (uint32_t)((kk >> 6) * 4096);
                uint32_t klb = (uint32_t)((kk & 63) * 2);
                uint32_t b00, b01, b10, b11, b20, b21;
                ldsm_x4(b00, b01, b10, b11,
                        Wb + wbase4 + khb + ((cb4 + klb) ^ swz4));
                ldsm_x2(b20, b21,
                        Wb + wbase2 + khb + ((cb2 + klb) ^ swz2));
                mma_m16n8k16(acc[0], af, b00, b01);
                mma_m16n8k16(acc[1], af, b10, b11);
                mma_m16n8k16(acc[2], af, b20, b21);
            }
            cs++; if (cs == STW) { cs = 0; cph ^= 1; }
        }

#pragma unroll
        for (int nt = 0; nt < 3; nt++) {
            int c = (wn * 3 + nt) * 8 + 2 * ti;
            int m = wm * 16 + g;
            gh_s[m * 100 + c]           = acc[nt][0];
            gh_s[m * 100 + c + 1]       = acc[nt][1];
            gh_s[(m + 8) * 100 + c]     = acc[nt][2];
            gh_s[(m + 8) * 100 + c + 1] = acc[nt][3];
        }
        __syncthreads();

        int tph = t & 3;
#pragma unroll
        for (int i = 0; i < 4; i++) {
            int idx = tid + i * 256;
            int b = pb[i], nl = pn[i] - n0, n = pn[i];

            float hr = gh_s[b * 100 + nl]      + bhr[i];
            float hz = gh_s[b * 100 + 32 + nl] + bhz[i];
            float hn = gh_s[b * 100 + 64 + nl] + bhn[i];

            float r = 1.f / (1.f + expf(-(pxr[i] + hr)));
            float z = 1.f / (1.f + expf(-(pxz[i] + hz)));
            float nn = tanhf(pxn[i] + r * hn);
            float hnew = (1.f - z) * nn + z * hreg[i];
            hreg[i] = hnew;

            Aout[b * NHH + n] = __float2half(hnew);
            sbuf[tph * 1024 + idx] = hnew;
            if (t == NTT - 1) d_out[OUT_HENC + b * NHH + n] = hnew;
        }

        if (t == NTT - 1) {
            // final states flush (t=99, tph==3)
#pragma unroll
            for (int i = 0; i < 4; i++) {
                int idx = tid + i * 256;
                int b = pb[i], n = pn[i];
                float4 v = make_float4(sbuf[idx], sbuf[1024 + idx],
                                       sbuf[2048 + idx], sbuf[3072 + idx]);
                __stcs((float4*)&d_out[OUT_STATES + (long)b * (NHH * NTT)
                                       + (long)n * NTT + (t - 3)], v);
            }
        } else {
            __syncthreads();
            bool released = false;
            unsigned target = barBase + (unsigned)(t + 1);
            if (tid == 0) {
                __threadfence();
                unsigned arrived = atomicAdd(&gBarCnt, 1u);
                if (arrived == NBLK - 1) {
                    gBarCnt = 0;
                    __threadfence();
                    atomicExch(&gBarPhase, target);
                    released = true;
                }
            }

            // ---- overlap the barrier wait ----
            if (tph == 3) {
#pragma unroll
                for (int i = 0; i < 4; i++) {
                    int idx = tid + i * 256;
                    int b = pb[i], n = pn[i];
                    float4 v = make_float4(sbuf[idx], sbuf[1024 + idx],
                                           sbuf[2048 + idx], sbuf[3072 + idx]);
                    __stcs((float4*)&d_out[OUT_STATES + (long)b * (NHH * NTT)
                                           + (long)n * NTT + (t - 3)], v);
                }
            }
            // next-step gx prefetch (barrier-independent)
#pragma unroll
            for (int i = 0; i < 4; i++) {
                long gxr = ((long)((t + 1) * NB + pb[i])) * NH3 + pn[i];
                pxr[i] = __ldcs(&gGx[gxr]);
                pxz[i] = __ldcs(&gGx[gxr + NHH]);
                pxn[i] = __ldcs(&gGx[gxr + 2 * NHH]);
            }

            if (tid == 0 && !released) {
                while ((int)(atomicAdd(&gBarPhase, 0u) - target) < 0) {
                    __nanosleep(32);
                }
            }
            __syncthreads();

            const __half* A2 = gHh[(t + 1) & 1];
#pragma unroll
            for (int s = 0; s < STA - 1; s++) {
#pragma unroll
                for (int j = 0; j < 2; j++)
                    cp_async16(As + (s * AR + ldrow + j * 16) * LDA + ldseg * 8,
                               A2 + aoffg[j] + s * BK);
                cp_commit();
            }
        }
    }
    cp_wait<0>();
}

// ------------------------- classifier ---------------------------------------
__global__ void classifier_kernel(const float* __restrict__ w1, const float* __restrict__ b1,
                                  const float* __restrict__ w2, const float* __restrict__ b2,
                                  float* __restrict__ d_out) {
    __shared__ float hid[300];
    int b = blockIdx.x;
    int tid = threadIdx.x, warp = tid >> 5, lane = tid & 31;
    const float* hb = d_out + OUT_HENC + (long)b * NHH;

    for (int j = warp; j < 300; j += 8) {
        float s = 0.f;
        for (int k = lane; k < NHH; k += 32) s += hb[k] * w1[(long)j * NHH + k];
#pragma unroll
        for (int off = 16; off; off >>= 1) s += __shfl_xor_sync(0xffffffffu, s, off);
        if (lane == 0) hid[j] = fmaxf(s + b1[j], 0.f);
    }
    __syncthreads();
    if (warp < 2) {
        float s = 0.f;
        for (int j = lane; j < 300; j += 32) s += hid[j] * w2[warp * 300 + j];
#pragma unroll
        for (int off = 16; off; off >>= 1) s += __shfl_xor_sync(0xffffffffu, s, off);
        if (lane == 0) d_out[OUT_CLS + b * 2 + warp] = s + b2[warp];
    }
}

// ------------------------- launch --------------------------------------------
extern "C" void kernel_launch(void* const* d_in, const int* in_sizes, int n_in,
                              void* d_out, int out_size) {
    const float* x      = (const float*)d_in[0];
    const float* adj    = (const float*)d_in[1];
    const float* h0     = (const float*)d_in[3];
    const float* conv_w = (const float*)d_in[4];
    const float* conv_b = (const float*)d_in[5];
    const float* w_ih   = (const float*)d_in[6];
    const float* w_hh   = (const float*)d_in[7];
    const float* b_ih   = (const float*)d_in[8];
    const float* b_hh   = (const float*)d_in[9];
    const float* cls_w1 = (const float*)d_in[10];
    const float* cls_b1 = (const float*)d_in[11];
    const float* cls_w2 = (const float*)d_in[12];
    const float* cls_b2 = (const float*)d_in[13];
    float* out = (float*)d_out;

    const int REPR_SMEM = (128 * 132 + 128 * 32 + 128 * 32 + 12 * 128) * 4;  // 106496
    const int GX_SMEM   = 3 * (128 + 128) * 72 * 2;                          // 110592
    const int PS_SMEM   = 195136 + 16384;                                    // 211520
    cudaFuncSetAttribute(repr_kernel, cudaFuncAttributeMaxDynamicSharedMemorySize, REPR_SMEM);
    cudaFuncSetAttribute(gemm_gx_kernel, cudaFuncAttributeMaxDynamicSharedMemorySize, GX_SMEM);
    cudaFuncSetAttribute(gru_persistent_kernel, cudaFuncAttributeMaxDynamicSharedMemorySize, PS_SMEM);

    // Launch order: repr at index 3 (the ncu capture slot).
    support_kernel<<<1, 128>>>(adj);
    wih_convert_kernel<<<2048, 256>>>((const float4*)w_ih);
    init_whh_kernel<<<12288, 256>>>(w_hh, h0);
    repr_kernel<<<NR, 256, REPR_SMEM>>>(x, conv_w, conv_b, out);
    gemm_gx_kernel<<<dim3(25, 96), 256, GX_SMEM>>>(b_ih);
    gru_persistent_kernel<<<NBLK, 256, PS_SMEM>>>(h0, b_hh, out);
    classifier_kernel<<<NB, 256>>>(cls_w1, cls_b1, cls_w2, cls_b2, out);
}